// round 5
// baseline (speedup 1.0000x reference)
#include <cuda_runtime.h>

#define TSTEPS 512
#define ISZ    8
#define HID    32
#define BC     64          // batch per CTA
#define NTH    256
#define PAIRS  4           // batch pairs per thread (8 batch per warp)
#define HP     68          // row pitch (floats), 16B-aligned rows

typedef unsigned long long u64;

struct __align__(16) SmemLayout {
    float4 wx0[ISZ][HID];   // [j][k] = W rows (k, k+32, k+64, k+96), col j
    float4 wh0[HID][HID];
    float4 wx1[HID][HID];
    float4 wh1[HID][HID];
    float  b0[128];         // bih0 + bhh0
    float  b1[128];         // bih1 + bhh1
    float  h1s[2][HID][HP]; // layer-0 hidden, double buffered, [unit][batch]
    float  h2s[2][HID][HP]; // layer-1 hidden
    float  xs[2][ISZ][HP];  // layernormed x, [feat][batch]
    float  fcW1[16 * HID];
    float  fcb1[16];
    float  fcW2[16];
    float  fcb2;
};

// ---------------- f32x2 helpers ----------------
__device__ __forceinline__ u64 dup2(float x) {
    u64 r; asm("mov.b64 %0,{%1,%1};" : "=l"(r) : "f"(x)); return r;
}
__device__ __forceinline__ u64 pk2(float a, float b) {
    u64 r; asm("mov.b64 %0,{%1,%2};" : "=l"(r) : "f"(a), "f"(b)); return r;
}
__device__ __forceinline__ void up2(u64 v, float& a, float& b) {
    asm("mov.b64 {%0,%1},%2;" : "=f"(a), "=f"(b) : "l"(v));
}
__device__ __forceinline__ u64 ffma2(u64 a, u64 b, u64 c) {
    u64 d; asm("fma.rn.f32x2 %0,%1,%2,%3;" : "=l"(d) : "l"(a), "l"(b), "l"(c)); return d;
}

// ---------------- fast transcendentals (accurate approx) ----------------
__device__ __forceinline__ float ex2a(float x) {
    float y; asm("ex2.approx.f32 %0,%1;" : "=f"(y) : "f"(x)); return y;
}
__device__ __forceinline__ float rcpa(float x) {
    float y; asm("rcp.approx.f32 %0,%1;" : "=f"(y) : "f"(x)); return y;
}
__device__ __forceinline__ float sigf(float x) {
    return rcpa(1.0f + ex2a(-1.4426950408889634f * x));
}
__device__ __forceinline__ float tanhfx(float x) {
    return 1.0f - 2.0f * rcpa(1.0f + ex2a(2.8853900817779268f * x));
}

// ---------------- gate accumulation (the hot loop) ----------------
template <int NJ>
__device__ __forceinline__ void gate_acc(const float4* __restrict__ Wq,
                                         const float* __restrict__ Xrow,
                                         int k, int wb, u64 acc[4][PAIRS]) {
#pragma unroll 8
    for (int j = 0; j < NJ; ++j) {
        const float4 w = Wq[j * HID + k];                 // 1x LDS.128, lane-strided
        u64 W0 = dup2(w.x);
        u64 W1 = dup2(w.y);
        u64 W2 = dup2(w.z);
        u64 W3 = dup2(w.w);
        const ulonglong2 xv0 =
            *reinterpret_cast<const ulonglong2*>(Xrow + j * HP + wb);      // pairs 0,1
        const ulonglong2 xv1 =
            *reinterpret_cast<const ulonglong2*>(Xrow + j * HP + wb + 4);  // pairs 2,3
        const u64 x0 = xv0.x, x1 = xv0.y, x2 = xv1.x, x3 = xv1.y;
        acc[0][0] = ffma2(W0, x0, acc[0][0]);
        acc[0][1] = ffma2(W0, x1, acc[0][1]);
        acc[0][2] = ffma2(W0, x2, acc[0][2]);
        acc[0][3] = ffma2(W0, x3, acc[0][3]);
        acc[1][0] = ffma2(W1, x0, acc[1][0]);
        acc[1][1] = ffma2(W1, x1, acc[1][1]);
        acc[1][2] = ffma2(W1, x2, acc[1][2]);
        acc[1][3] = ffma2(W1, x3, acc[1][3]);
        acc[2][0] = ffma2(W2, x0, acc[2][0]);
        acc[2][1] = ffma2(W2, x1, acc[2][1]);
        acc[2][2] = ffma2(W2, x2, acc[2][2]);
        acc[2][3] = ffma2(W2, x3, acc[2][3]);
        acc[3][0] = ffma2(W3, x0, acc[3][0]);
        acc[3][1] = ffma2(W3, x1, acc[3][1]);
        acc[3][2] = ffma2(W3, x2, acc[3][2]);
        acc[3][3] = ffma2(W3, x3, acc[3][3]);
    }
}

// gates (i,f,g,o as f32x2 over a batch pair) + cell state -> new h (f32x2)
__device__ __forceinline__ u64 lstm_act(u64 gi, u64 gf, u64 gg, u64 go, u64& c) {
    float a, b;
    up2(gi, a, b); float i0 = sigf(a),   i1 = sigf(b);
    up2(gf, a, b); float f0 = sigf(a),   f1 = sigf(b);
    up2(gg, a, b); float g0 = tanhfx(a), g1 = tanhfx(b);
    up2(go, a, b); float o0 = sigf(a),   o1 = sigf(b);
    float c0, c1; up2(c, c0, c1);
    c0 = f0 * c0 + i0 * g0;
    c1 = f1 * c1 + i1 * g1;
    c = pk2(c0, c1);
    float h0 = o0 * tanhfx(c0);
    float h1 = o1 * tanhfx(c1);
    return pk2(h0, h1);
}

extern __shared__ char smem_raw[];

__global__ void __launch_bounds__(NTH, 1)
lstm_model_kernel(const float* __restrict__ x,
                  const float* __restrict__ ln_g, const float* __restrict__ ln_b,
                  const float* __restrict__ Wih0, const float* __restrict__ Whh0,
                  const float* __restrict__ bih0, const float* __restrict__ bhh0,
                  const float* __restrict__ Wih1, const float* __restrict__ Whh1,
                  const float* __restrict__ bih1, const float* __restrict__ bhh1,
                  const float* __restrict__ W1, const float* __restrict__ b1,
                  const float* __restrict__ W2, const float* __restrict__ b2,
                  float* __restrict__ out)
{
    SmemLayout& S = *reinterpret_cast<SmemLayout*>(smem_raw);
    const int tid = threadIdx.x;
    const int k   = tid & 31;   // hidden unit
    const int w   = tid >> 5;   // warp id
    const int wb  = 8 * w;      // warp's batch base within CTA
    const int bc0 = blockIdx.x * BC;

    // ---- prologue: stage weights repacked as [j][k] float4 ----
    for (int idx = tid; idx < HID * ISZ; idx += NTH) {
        int kk = idx & 31, j = idx >> 5;
        S.wx0[j][kk] = make_float4(Wih0[kk * ISZ + j],        Wih0[(kk + 32) * ISZ + j],
                                   Wih0[(kk + 64) * ISZ + j], Wih0[(kk + 96) * ISZ + j]);
    }
    for (int idx = tid; idx < HID * HID; idx += NTH) {
        int kk = idx & 31, j = idx >> 5;
        S.wh0[j][kk] = make_float4(Whh0[kk * HID + j],        Whh0[(kk + 32) * HID + j],
                                   Whh0[(kk + 64) * HID + j], Whh0[(kk + 96) * HID + j]);
        S.wx1[j][kk] = make_float4(Wih1[kk * HID + j],        Wih1[(kk + 32) * HID + j],
                                   Wih1[(kk + 64) * HID + j], Wih1[(kk + 96) * HID + j]);
        S.wh1[j][kk] = make_float4(Whh1[kk * HID + j],        Whh1[(kk + 32) * HID + j],
                                   Whh1[(kk + 64) * HID + j], Whh1[(kk + 96) * HID + j]);
    }
    for (int idx = tid; idx < 128; idx += NTH) {
        S.b0[idx] = bih0[idx] + bhh0[idx];
        S.b1[idx] = bih1[idx] + bhh1[idx];
    }
    for (int idx = tid; idx < 16 * HID; idx += NTH) S.fcW1[idx] = W1[idx];
    if (tid < 16) { S.fcb1[tid] = b1[tid]; S.fcW2[tid] = W2[tid]; }
    if (tid == 0) S.fcb2 = b2[0];
    for (int idx = tid; idx < 2 * HID * HP; idx += NTH) {
        (&S.h1s[0][0][0])[idx] = 0.0f;
        (&S.h2s[0][0][0])[idx] = 0.0f;
    }

    // ---- this thread's x-load / layernorm slice (warp-local by construction) ----
    const int   lb   = tid >> 2;          // batch 0..63 (warp w owns 8w..8w+7)
    const int   li   = (tid & 3) * 2;     // feature offset 0,2,4,6
    const float lg0  = ln_g[li],  lg1  = ln_g[li + 1];
    const float lbb0 = ln_b[li],  lbb1 = ln_b[li + 1];
    const float* xg  = x + (size_t)(bc0 + lb) * TSTEPS * ISZ + li;

    // load + LN x[t=0] into xs[0]
    {
        float2 v = *reinterpret_cast<const float2*>(xg);
        float s  = v.x + v.y;
        float ss = v.x * v.x + v.y * v.y;
        s  += __shfl_xor_sync(0xffffffffu, s, 1);
        ss += __shfl_xor_sync(0xffffffffu, ss, 1);
        s  += __shfl_xor_sync(0xffffffffu, s, 2);
        ss += __shfl_xor_sync(0xffffffffu, ss, 2);
        float mu  = s * 0.125f;
        float var = ss * 0.125f - mu * mu;
        float rs  = rsqrtf(var + 1e-5f);
        S.xs[0][li][lb]     = (v.x - mu) * rs * lg0 + lbb0;
        S.xs[0][li + 1][lb] = (v.y - mu) * rs * lg1 + lbb1;
    }
    __syncthreads();   // weights + zeroed state + xs[0] visible to everyone once

    u64 c1s[PAIRS] = {0, 0, 0, 0};
    u64 c2s[PAIRS] = {0, 0, 0, 0};
    u64 accA[4][PAIRS];
    u64 accB[4][PAIRS];
    float2 xn = make_float2(0.f, 0.f);

    // ---------- P(t): fma-heavy half (layer-0 GEMM + layer-1 recurrent GEMM) ----
    auto phaseP = [&](int t) {
        const int cur = t & 1;
        const int oth = cur ^ 1;
        // prefetch raw x[t+1] (consumed in Q(t))
        if (t + 1 < TSTEPS)
            xn = *reinterpret_cast<const float2*>(xg + (size_t)(t + 1) * ISZ);
#pragma unroll
        for (int g = 0; g < 4; ++g) {
            u64 bbA = dup2(S.b0[g * 32 + k]);
            u64 bbB = dup2(S.b1[g * 32 + k]);
#pragma unroll
            for (int p = 0; p < PAIRS; ++p) { accA[g][p] = bbA; accB[g][p] = bbB; }
        }
        gate_acc<ISZ>(&S.wx0[0][0], &S.xs[cur][0][0],  k, wb, accA);
        gate_acc<HID>(&S.wh0[0][0], &S.h1s[oth][0][0], k, wb, accA);
        gate_acc<HID>(&S.wh1[0][0], &S.h2s[oth][0][0], k, wb, accB);
    };

    // ---------- Q(t): MUFU-heavy half (act-0, LN, layer-1 input GEMM, act-1) ----
    auto phaseQ = [&](int t) {
        const int cur = t & 1;
        const int oth = cur ^ 1;
#pragma unroll
        for (int p = 0; p < PAIRS; ++p) {
            u64 hv = lstm_act(accA[0][p], accA[1][p], accA[2][p], accA[3][p], c1s[p]);
            *reinterpret_cast<u64*>(&S.h1s[cur][k][wb + 2 * p]) = hv;
        }
        if (t + 1 < TSTEPS) {
            float s  = xn.x + xn.y;
            float ss = xn.x * xn.x + xn.y * xn.y;
            s  += __shfl_xor_sync(0xffffffffu, s, 1);
            ss += __shfl_xor_sync(0xffffffffu, ss, 1);
            s  += __shfl_xor_sync(0xffffffffu, s, 2);
            ss += __shfl_xor_sync(0xffffffffu, ss, 2);
            float mu  = s * 0.125f;
            float var = ss * 0.125f - mu * mu;
            float rs  = rsqrtf(var + 1e-5f);
            S.xs[oth][li][lb]     = (xn.x - mu) * rs * lg0 + lbb0;
            S.xs[oth][li + 1][lb] = (xn.y - mu) * rs * lg1 + lbb1;
        }
        __syncwarp();   // h1s[cur] + xs[oth] warp-local visibility
        gate_acc<HID>(&S.wx1[0][0], &S.h1s[cur][0][0], k, wb, accB);
#pragma unroll
        for (int p = 0; p < PAIRS; ++p) {
            u64 hv = lstm_act(accB[0][p], accB[1][p], accB[2][p], accB[3][p], c2s[p]);
            *reinterpret_cast<u64*>(&S.h2s[cur][k][wb + 2 * p]) = hv;
        }
        __syncwarp();
    };

    // ---- anti-phase staggering: even warps P;Q — odd warps Q;P(+1) ----
    if ((w & 1) == 0) {
        for (int t = 0; t < TSTEPS; ++t) {
            phaseP(t);
            phaseQ(t);
        }
    } else {
        phaseP(0);
        for (int t = 0; t < TSTEPS; ++t) {
            phaseQ(t);
            if (t + 1 < TSTEPS) phaseP(t + 1);
        }
    }

    __syncthreads();   // FC head reads h2s across warps

    // ---------- FC head: out = tanh(relu(h2 @ W1^T + b1) @ W2^T + b2) ----------
    if (tid < BC) {
        float hv[HID];
#pragma unroll
        for (int kk = 0; kk < HID; ++kk)
            hv[kk] = S.h2s[(TSTEPS - 1) & 1][kk][tid];
        float acc2 = S.fcb2;
#pragma unroll
        for (int f = 0; f < 16; ++f) {
            float s = S.fcb1[f];
#pragma unroll
            for (int kk = 0; kk < HID; ++kk)
                s += hv[kk] * S.fcW1[f * HID + kk];
            s = fmaxf(s, 0.0f);
            acc2 += s * S.fcW2[f];
        }
        out[bc0 + tid] = tanhfx(acc2);
    }
}

extern "C" void kernel_launch(void* const* d_in, const int* in_sizes, int n_in,
                              void* d_out, int out_size) {
    const float* x    = (const float*)d_in[0];
    const float* ln_g = (const float*)d_in[1];
    const float* ln_b = (const float*)d_in[2];
    const float* Wih0 = (const float*)d_in[3];
    const float* Whh0 = (const float*)d_in[4];
    const float* bih0 = (const float*)d_in[5];
    const float* bhh0 = (const float*)d_in[6];
    const float* Wih1 = (const float*)d_in[7];
    const float* Whh1 = (const float*)d_in[8];
    const float* bih1 = (const float*)d_in[9];
    const float* bhh1 = (const float*)d_in[10];
    const float* W1   = (const float*)d_in[11];
    const float* b1   = (const float*)d_in[12];
    const float* W2   = (const float*)d_in[13];
    const float* b2   = (const float*)d_in[14];
    float* out = (float*)d_out;

    const int nb   = in_sizes[0] / (TSTEPS * ISZ);  // batch size (8192)
    const int grid = nb / BC;                       // 128 CTAs
    const size_t smem = sizeof(SmemLayout);

    cudaFuncSetAttribute(lstm_model_kernel,
                         cudaFuncAttributeMaxDynamicSharedMemorySize, (int)smem);

    lstm_model_kernel<<<grid, NTH, smem>>>(
        x, ln_g, ln_b, Wih0, Whh0, bih0, bhh0,
        Wih1, Whh1, bih1, bhh1, W1, b1, W2, b2, out);
}

// round 6
// speedup vs baseline: 1.0422x; 1.0422x over previous
#include <cuda_runtime.h>

#define TSTEPS 512
#define ISZ    8
#define HID    32
#define BC     64          // batch per CTA
#define NTH    256
#define PAIRS  4           // batch pairs per thread (8 batch per warp)
#define HP     68          // row pitch (floats), 16B-aligned rows

typedef unsigned long long u64;

struct __align__(16) SmemLayout {
    float4 wx0[ISZ][HID];   // [j][k] = W rows (k, k+32, k+64, k+96), col j
    float4 wh0[HID][HID];
    float4 wx1[HID][HID];
    float4 wh1[HID][HID];
    float  b0[128];         // bih0 + bhh0
    float  b1[128];         // bih1 + bhh1
    float  h1s[2][HID][HP]; // layer-0 hidden, double buffered, [unit][batch]
    float  h2s[2][HID][HP]; // layer-1 hidden
    float  xs[2][ISZ][HP];  // layernormed x, [feat][batch]
    float  fcW1[16 * HID];
    float  fcb1[16];
    float  fcW2[16];
    float  fcb2;
};

// ---------------- f32x2 helpers ----------------
__device__ __forceinline__ u64 dup2(float x) {
    u64 r; asm("mov.b64 %0,{%1,%1};" : "=l"(r) : "f"(x)); return r;
}
__device__ __forceinline__ u64 pk2(float a, float b) {
    u64 r; asm("mov.b64 %0,{%1,%2};" : "=l"(r) : "f"(a), "f"(b)); return r;
}
__device__ __forceinline__ void up2(u64 v, float& a, float& b) {
    asm("mov.b64 {%0,%1},%2;" : "=f"(a), "=f"(b) : "l"(v));
}
__device__ __forceinline__ u64 ffma2(u64 a, u64 b, u64 c) {
    u64 d; asm("fma.rn.f32x2 %0,%1,%2,%3;" : "=l"(d) : "l"(a), "l"(b), "l"(c)); return d;
}

// ---------------- fast transcendentals (accurate approx) ----------------
__device__ __forceinline__ float ex2a(float x) {
    float y; asm("ex2.approx.f32 %0,%1;" : "=f"(y) : "f"(x)); return y;
}
__device__ __forceinline__ float rcpa(float x) {
    float y; asm("rcp.approx.f32 %0,%1;" : "=f"(y) : "f"(x)); return y;
}
__device__ __forceinline__ float sigf(float x) {
    return rcpa(1.0f + ex2a(-1.4426950408889634f * x));
}
__device__ __forceinline__ float tanhfx(float x) {
    return 1.0f - 2.0f * rcpa(1.0f + ex2a(2.8853900817779268f * x));
}

// ---------------- gate accumulation (the hot loop) ----------------
template <int NJ>
__device__ __forceinline__ void gate_acc(const float4* __restrict__ Wq,
                                         const float* __restrict__ Xrow,
                                         int k, int wb, u64 acc[4][PAIRS]) {
#pragma unroll 8
    for (int j = 0; j < NJ; ++j) {
        const float4 w = Wq[j * HID + k];                 // 1x LDS.128, lane-strided
        u64 W0 = dup2(w.x);
        u64 W1 = dup2(w.y);
        u64 W2 = dup2(w.z);
        u64 W3 = dup2(w.w);
        const ulonglong2 xv0 =
            *reinterpret_cast<const ulonglong2*>(Xrow + j * HP + wb);      // pairs 0,1
        const ulonglong2 xv1 =
            *reinterpret_cast<const ulonglong2*>(Xrow + j * HP + wb + 4);  // pairs 2,3
        const u64 x0 = xv0.x, x1 = xv0.y, x2 = xv1.x, x3 = xv1.y;
        acc[0][0] = ffma2(W0, x0, acc[0][0]);
        acc[0][1] = ffma2(W0, x1, acc[0][1]);
        acc[0][2] = ffma2(W0, x2, acc[0][2]);
        acc[0][3] = ffma2(W0, x3, acc[0][3]);
        acc[1][0] = ffma2(W1, x0, acc[1][0]);
        acc[1][1] = ffma2(W1, x1, acc[1][1]);
        acc[1][2] = ffma2(W1, x2, acc[1][2]);
        acc[1][3] = ffma2(W1, x3, acc[1][3]);
        acc[2][0] = ffma2(W2, x0, acc[2][0]);
        acc[2][1] = ffma2(W2, x1, acc[2][1]);
        acc[2][2] = ffma2(W2, x2, acc[2][2]);
        acc[2][3] = ffma2(W2, x3, acc[2][3]);
        acc[3][0] = ffma2(W3, x0, acc[3][0]);
        acc[3][1] = ffma2(W3, x1, acc[3][1]);
        acc[3][2] = ffma2(W3, x2, acc[3][2]);
        acc[3][3] = ffma2(W3, x3, acc[3][3]);
    }
}

// gates (i,f,g,o as f32x2 over a batch pair) + cell state -> new h (f32x2)
__device__ __forceinline__ u64 lstm_act(u64 gi, u64 gf, u64 gg, u64 go, u64& c) {
    float a, b;
    up2(gi, a, b); float i0 = sigf(a),   i1 = sigf(b);
    up2(gf, a, b); float f0 = sigf(a),   f1 = sigf(b);
    up2(gg, a, b); float g0 = tanhfx(a), g1 = tanhfx(b);
    up2(go, a, b); float o0 = sigf(a),   o1 = sigf(b);
    float c0, c1; up2(c, c0, c1);
    c0 = f0 * c0 + i0 * g0;
    c1 = f1 * c1 + i1 * g1;
    c = pk2(c0, c1);
    float h0 = o0 * tanhfx(c0);
    float h1 = o1 * tanhfx(c1);
    return pk2(h0, h1);
}

extern __shared__ char smem_raw[];

__global__ void __launch_bounds__(NTH, 1)
lstm_model_kernel(const float* __restrict__ x,
                  const float* __restrict__ ln_g, const float* __restrict__ ln_b,
                  const float* __restrict__ Wih0, const float* __restrict__ Whh0,
                  const float* __restrict__ bih0, const float* __restrict__ bhh0,
                  const float* __restrict__ Wih1, const float* __restrict__ Whh1,
                  const float* __restrict__ bih1, const float* __restrict__ bhh1,
                  const float* __restrict__ W1, const float* __restrict__ b1,
                  const float* __restrict__ W2, const float* __restrict__ b2,
                  float* __restrict__ out)
{
    SmemLayout& S = *reinterpret_cast<SmemLayout*>(smem_raw);
    const int tid = threadIdx.x;
    const int k   = tid & 31;   // hidden unit
    const int w   = tid >> 5;   // warp id
    const int wb  = 8 * w;      // warp's batch base within CTA
    const int bc0 = blockIdx.x * BC;

    // ---- prologue: stage weights repacked as [j][k] float4 ----
    for (int idx = tid; idx < HID * ISZ; idx += NTH) {
        int kk = idx & 31, j = idx >> 5;
        S.wx0[j][kk] = make_float4(Wih0[kk * ISZ + j],        Wih0[(kk + 32) * ISZ + j],
                                   Wih0[(kk + 64) * ISZ + j], Wih0[(kk + 96) * ISZ + j]);
    }
    for (int idx = tid; idx < HID * HID; idx += NTH) {
        int kk = idx & 31, j = idx >> 5;
        S.wh0[j][kk] = make_float4(Whh0[kk * HID + j],        Whh0[(kk + 32) * HID + j],
                                   Whh0[(kk + 64) * HID + j], Whh0[(kk + 96) * HID + j]);
        S.wx1[j][kk] = make_float4(Wih1[kk * HID + j],        Wih1[(kk + 32) * HID + j],
                                   Wih1[(kk + 64) * HID + j], Wih1[(kk + 96) * HID + j]);
        S.wh1[j][kk] = make_float4(Whh1[kk * HID + j],        Whh1[(kk + 32) * HID + j],
                                   Whh1[(kk + 64) * HID + j], Whh1[(kk + 96) * HID + j]);
    }
    for (int idx = tid; idx < 128; idx += NTH) {
        S.b0[idx] = bih0[idx] + bhh0[idx];
        S.b1[idx] = bih1[idx] + bhh1[idx];
    }
    for (int idx = tid; idx < 16 * HID; idx += NTH) S.fcW1[idx] = W1[idx];
    if (tid < 16) { S.fcb1[tid] = b1[tid]; S.fcW2[tid] = W2[tid]; }
    if (tid == 0) S.fcb2 = b2[0];
    for (int idx = tid; idx < 2 * HID * HP; idx += NTH) {
        (&S.h1s[0][0][0])[idx] = 0.0f;
        (&S.h2s[0][0][0])[idx] = 0.0f;
    }

    // ---- this thread's x-load / layernorm slice (warp-local by construction) ----
    const int   lb   = tid >> 2;          // batch 0..63 (warp w owns 8w..8w+7)
    const int   li   = (tid & 3) * 2;     // feature offset 0,2,4,6
    const float lg0  = ln_g[li],  lg1  = ln_g[li + 1];
    const float lbb0 = ln_b[li],  lbb1 = ln_b[li + 1];
    const float* xg  = x + (size_t)(bc0 + lb) * TSTEPS * ISZ + li;

    // load + LN x[t=0] into xs[0]
    {
        float2 v = *reinterpret_cast<const float2*>(xg);
        float s  = v.x + v.y;
        float ss = v.x * v.x + v.y * v.y;
        s  += __shfl_xor_sync(0xffffffffu, s, 1);
        ss += __shfl_xor_sync(0xffffffffu, ss, 1);
        s  += __shfl_xor_sync(0xffffffffu, s, 2);
        ss += __shfl_xor_sync(0xffffffffu, ss, 2);
        float mu  = s * 0.125f;
        float var = ss * 0.125f - mu * mu;
        float rs  = rsqrtf(var + 1e-5f);
        S.xs[0][li][lb]     = (v.x - mu) * rs * lg0 + lbb0;
        S.xs[0][li + 1][lb] = (v.y - mu) * rs * lg1 + lbb1;
    }
    __syncthreads();   // weights + zeroed state + xs[0] visible to everyone once

    u64 c1s[PAIRS] = {0, 0, 0, 0};
    u64 c2s[PAIRS] = {0, 0, 0, 0};
    u64 accA[4][PAIRS];
    u64 accB[4][PAIRS];
    float2 xn = make_float2(0.f, 0.f);

    // ---------- P(t): fma-heavy half (layer-0 GEMM + layer-1 recurrent GEMM) ----
    auto phaseP = [&](int t) {
        const int cur = t & 1;
        const int oth = cur ^ 1;
        // prefetch raw x[t+1] (consumed in Q(t))
        if (t + 1 < TSTEPS)
            xn = *reinterpret_cast<const float2*>(xg + (size_t)(t + 1) * ISZ);
#pragma unroll
        for (int g = 0; g < 4; ++g) {
            u64 bbA = dup2(S.b0[g * 32 + k]);
            u64 bbB = dup2(S.b1[g * 32 + k]);
#pragma unroll
            for (int p = 0; p < PAIRS; ++p) { accA[g][p] = bbA; accB[g][p] = bbB; }
        }
        gate_acc<ISZ>(&S.wx0[0][0], &S.xs[cur][0][0],  k, wb, accA);
        gate_acc<HID>(&S.wh0[0][0], &S.h1s[oth][0][0], k, wb, accA);
        gate_acc<HID>(&S.wh1[0][0], &S.h2s[oth][0][0], k, wb, accB);
    };

    // ---------- Q(t): MUFU-heavy half (act-0, LN, layer-1 input GEMM, act-1) ----
    auto phaseQ = [&](int t) {
        const int cur = t & 1;
        const int oth = cur ^ 1;
#pragma unroll
        for (int p = 0; p < PAIRS; ++p) {
            u64 hv = lstm_act(accA[0][p], accA[1][p], accA[2][p], accA[3][p], c1s[p]);
            *reinterpret_cast<u64*>(&S.h1s[cur][k][wb + 2 * p]) = hv;
        }
        if (t + 1 < TSTEPS) {
            float s  = xn.x + xn.y;
            float ss = xn.x * xn.x + xn.y * xn.y;
            s  += __shfl_xor_sync(0xffffffffu, s, 1);
            ss += __shfl_xor_sync(0xffffffffu, ss, 1);
            s  += __shfl_xor_sync(0xffffffffu, s, 2);
            ss += __shfl_xor_sync(0xffffffffu, ss, 2);
            float mu  = s * 0.125f;
            float var = ss * 0.125f - mu * mu;
            float rs  = rsqrtf(var + 1e-5f);
            S.xs[oth][li][lb]     = (xn.x - mu) * rs * lg0 + lbb0;
            S.xs[oth][li + 1][lb] = (xn.y - mu) * rs * lg1 + lbb1;
        }
        __syncwarp();   // h1s[cur] + xs[oth] warp-local visibility
        gate_acc<HID>(&S.wx1[0][0], &S.h1s[cur][0][0], k, wb, accB);
#pragma unroll
        for (int p = 0; p < PAIRS; ++p) {
            u64 hv = lstm_act(accB[0][p], accB[1][p], accB[2][p], accB[3][p], c2s[p]);
            *reinterpret_cast<u64*>(&S.h2s[cur][k][wb + 2 * p]) = hv;
        }
        __syncwarp();
    };

    // ---- anti-phase staggering keyed on SMSP partnership ----
    // SMSP = wid % 4, so warps (w, w+4) share an SMSP. Splitting on w>>2
    // puts exactly one P-phase and one Q-phase warp on every SMSP.
    if (w < 4) {
        for (int t = 0; t < TSTEPS; ++t) {
            phaseP(t);
            phaseQ(t);
        }
    } else {
        phaseP(0);
        for (int t = 0; t < TSTEPS; ++t) {
            phaseQ(t);
            if (t + 1 < TSTEPS) phaseP(t + 1);
        }
    }

    __syncthreads();   // FC head reads h2s across warps

    // ---------- FC head: out = tanh(relu(h2 @ W1^T + b1) @ W2^T + b2) ----------
    if (tid < BC) {
        float hv[HID];
#pragma unroll
        for (int kk = 0; kk < HID; ++kk)
            hv[kk] = S.h2s[(TSTEPS - 1) & 1][kk][tid];
        float acc2 = S.fcb2;
#pragma unroll
        for (int f = 0; f < 16; ++f) {
            float s = S.fcb1[f];
#pragma unroll
            for (int kk = 0; kk < HID; ++kk)
                s += hv[kk] * S.fcW1[f * HID + kk];
            s = fmaxf(s, 0.0f);
            acc2 += s * S.fcW2[f];
        }
        out[bc0 + tid] = tanhfx(acc2);
    }
}

extern "C" void kernel_launch(void* const* d_in, const int* in_sizes, int n_in,
                              void* d_out, int out_size) {
    const float* x    = (const float*)d_in[0];
    const float* ln_g = (const float*)d_in[1];
    const float* ln_b = (const float*)d_in[2];
    const float* Wih0 = (const float*)d_in[3];
    const float* Whh0 = (const float*)d_in[4];
    const float* bih0 = (const float*)d_in[5];
    const float* bhh0 = (const float*)d_in[6];
    const float* Wih1 = (const float*)d_in[7];
    const float* Whh1 = (const float*)d_in[8];
    const float* bih1 = (const float*)d_in[9];
    const float* bhh1 = (const float*)d_in[10];
    const float* W1   = (const float*)d_in[11];
    const float* b1   = (const float*)d_in[12];
    const float* W2   = (const float*)d_in[13];
    const float* b2   = (const float*)d_in[14];
    float* out = (float*)d_out;

    const int nb   = in_sizes[0] / (TSTEPS * ISZ);  // batch size (8192)
    const int grid = nb / BC;                       // 128 CTAs
    const size_t smem = sizeof(SmemLayout);

    cudaFuncSetAttribute(lstm_model_kernel,
                         cudaFuncAttributeMaxDynamicSharedMemorySize, (int)smem);

    lstm_model_kernel<<<grid, NTH, smem>>>(
        x, ln_g, ln_b, Wih0, Whh0, bih0, bhh0,
        Wih1, Whh1, bih1, bhh1, W1, b1, W2, b2, out);
}